// round 3
// baseline (speedup 1.0000x reference)
#include <cuda_runtime.h>
#include <cstdint>
#include <cstddef>

#define NSN  100000
#define NMD  50000
#define EE   600000
#define D    128
#define HOR  8
#define NEG  0.2f
#define GLOG 256   // blocks for k_logits (must match partial arrays)

// ---------------- device scratch (no runtime allocation allowed) ----------------
__device__ float    d_xl[(size_t)NSN * D];     // 51.2 MB
__device__ float    d_xr[(size_t)NMD * D];     // 25.6 MB
__device__ float    d_ew[EE];                  // edge scores -> exp weights
__device__ unsigned d_menc[NMD];               // ordered-uint encoded segment max
__device__ float    d_ssum[NMD];               // segment sum of exp
__device__ float    d_gacc[D];                 // pooled accumulator
__device__ float    d_inp[D];                  // LSTM input
__device__ float    d_h[D];
__device__ float    d_c[D];
__device__ float    d_h2[D];                   // relu(pred layer1)
__device__ float    d_logits[NMD];
__device__ float    d_pm_best[GLOG];
__device__ int      d_pm_bi[GLOG];
__device__ float    d_pm_lm[GLOG];
__device__ float    d_pm_ls[GLOG];
__device__ uint2    d_keys[HOR];
__device__ int      d_is64;

// ---------------- helpers ----------------
__device__ __forceinline__ int eidx(const void* ei, int is64, long long pos) {
    return is64 ? (int)((const long long*)ei)[pos] : ((const int*)ei)[pos];
}
__device__ __forceinline__ unsigned encf(float f) {
    unsigned b = __float_as_uint(f);
    return (b & 0x80000000u) ? ~b : (b | 0x80000000u);
}
__device__ __forceinline__ float decf(unsigned u) {
    return (u >> 31) ? __uint_as_float(u ^ 0x80000000u) : __uint_as_float(~u);
}

// JAX threefry2x32, 20 rounds (matches jax/_src/prng.py)
__device__ __forceinline__ uint2 tf2x32(unsigned k0, unsigned k1, unsigned x0, unsigned x1) {
    unsigned k2 = k0 ^ k1 ^ 0x1BD11BDAu;
    x0 += k0; x1 += k1;
#define TFR(r) { x0 += x1; x1 = (x1 << (r)) | (x1 >> (32 - (r))); x1 ^= x0; }
    TFR(13) TFR(15) TFR(26) TFR(6)   x0 += k1; x1 += k2 + 1u;
    TFR(17) TFR(29) TFR(16) TFR(24)  x0 += k2; x1 += k0 + 2u;
    TFR(13) TFR(15) TFR(26) TFR(6)   x0 += k0; x1 += k1 + 3u;
    TFR(17) TFR(29) TFR(16) TFR(24)  x0 += k1; x1 += k2 + 4u;
    TFR(13) TFR(15) TFR(26) TFR(6)   x0 += k2; x1 += k0 + 5u;
#undef TFR
    return make_uint2(x0, x1);
}

// ---------------- init ----------------
__global__ void k_init(const void* ei) {
    int i = blockIdx.x * blockDim.x + threadIdx.x;
    if (i < NMD) { d_ssum[i] = 0.f; d_menc[i] = 0x007FFFFFu; }  // enc(-inf)
    if (i < D)   { d_gacc[i] = 0.f; d_h[i] = 0.f; d_c[i] = 0.f; }
    if (i == 0) {
        // detect int64 vs int32 edge_index: int64 => all high words zero
        const int* p = (const int*)ei;
        int all0 = 1;
        for (int j = 1; j < 201; j += 2) all0 &= (p[j] == 0);
        d_is64 = all0;
        // PARTITIONABLE threefry (JAX >= 0.5 default):
        // split(key(42), 8): counter = 64-bit iota split hi/lo => (0, j);
        // keys[j] = (out.x, out.y) of one threefry call.
        for (int j = 0; j < 8; j++) {
            uint2 r = tf2x32(0u, 42u, 0u, (unsigned)j);
            d_keys[j] = make_uint2(r.x, r.y);
        }
    }
}

// ---------------- GEMM: Y[r][c] = sum_k X[r][k]*W[c][k] ----------------
__global__ void __launch_bounds__(256) k_gemm(const float* __restrict__ X,
                                              const float* __restrict__ W,
                                              float* __restrict__ Y, int rows) {
    extern __shared__ float sm[];
    float* Ws = sm;               // [128][132] : Ws[k][col] = W[col][k]
    float* Xs = sm + 128 * 132;   // [64][132]
    for (int i = threadIdx.x; i < D * D; i += 256) {
        int col = i >> 7, k = i & 127;
        Ws[k * 132 + col] = W[i];
    }
    __syncthreads();
    int tx = threadIdx.x & 31, ty = threadIdx.x >> 5;
    int row0 = blockIdx.x << 6;
    int nr = rows - row0; if (nr > 64) nr = 64;
    for (int i = threadIdx.x * 4; i < 64 * D; i += 1024) {
        int r = i >> 7, c = i & 127;
        float4 v = make_float4(0.f, 0.f, 0.f, 0.f);
        if (r < nr) v = *(const float4*)(X + (size_t)(row0 + r) * D + c);
        *(float4*)(Xs + r * 132 + c) = v;
    }
    __syncthreads();
    float acc[8][4];
#pragma unroll
    for (int ri = 0; ri < 8; ri++) { acc[ri][0] = acc[ri][1] = acc[ri][2] = acc[ri][3] = 0.f; }
#pragma unroll 2
    for (int k = 0; k < D; k += 4) {
        float4 b0 = *(const float4*)(Ws + (k + 0) * 132 + tx * 4);
        float4 b1 = *(const float4*)(Ws + (k + 1) * 132 + tx * 4);
        float4 b2 = *(const float4*)(Ws + (k + 2) * 132 + tx * 4);
        float4 b3 = *(const float4*)(Ws + (k + 3) * 132 + tx * 4);
#pragma unroll
        for (int ri = 0; ri < 8; ri++) {
            float4 a = *(const float4*)(Xs + (ty * 8 + ri) * 132 + k);
            acc[ri][0] += a.x * b0.x + a.y * b1.x + a.z * b2.x + a.w * b3.x;
            acc[ri][1] += a.x * b0.y + a.y * b1.y + a.z * b2.y + a.w * b3.y;
            acc[ri][2] += a.x * b0.z + a.y * b1.z + a.z * b2.z + a.w * b3.z;
            acc[ri][3] += a.x * b0.w + a.y * b1.w + a.z * b2.w + a.w * b3.w;
        }
    }
#pragma unroll
    for (int ri = 0; ri < 8; ri++) {
        int r = row0 + ty * 8 + ri;
        if (r < rows)
            *(float4*)(Y + (size_t)r * D + tx * 4) =
                make_float4(acc[ri][0], acc[ri][1], acc[ri][2], acc[ri][3]);
    }
}

// ---------------- edge pass 1: e = att . leakyrelu(xl[src]+xr[dst]); segmax ----------------
__global__ void k_edge1(const void* __restrict__ ei, const float* __restrict__ att) {
    int lane = threadIdx.x & 31;
    int wid = (blockIdx.x * blockDim.x + threadIdx.x) >> 5;
    int nw = (gridDim.x * blockDim.x) >> 5;
    int is64 = d_is64;
    float a0 = att[lane], a1 = att[lane + 32], a2 = att[lane + 64], a3 = att[lane + 96];
    for (int e = wid; e < EE; e += nw) {
        int src = eidx(ei, is64, e);
        int dst = eidx(ei, is64, (long long)EE + e);
        const float* xl = d_xl + (size_t)src * D;
        const float* xr = d_xr + (size_t)dst * D;
        float z, p = 0.f;
        z = xl[lane +  0] + xr[lane +  0]; p += a0 * (z > 0.f ? z : NEG * z);
        z = xl[lane + 32] + xr[lane + 32]; p += a1 * (z > 0.f ? z : NEG * z);
        z = xl[lane + 64] + xr[lane + 64]; p += a2 * (z > 0.f ? z : NEG * z);
        z = xl[lane + 96] + xr[lane + 96]; p += a3 * (z > 0.f ? z : NEG * z);
#pragma unroll
        for (int o = 16; o; o >>= 1) p += __shfl_xor_sync(~0u, p, o);
        if (lane == 0) {
            d_ew[e] = p;
            atomicMax(&d_menc[dst], encf(p));
        }
    }
}

// ---------------- edge pass 2: ex = exp(e - m[dst]); segsum ----------------
__global__ void k_edge2(const void* __restrict__ ei) {
    int i = blockIdx.x * blockDim.x + threadIdx.x;
    if (i >= EE) return;
    int is64 = d_is64;
    int dst = eidx(ei, is64, (long long)EE + i);
    float m = decf(d_menc[dst]);
    float ex = expf(d_ew[i] - m);
    d_ew[i] = ex;
    atomicAdd(&d_ssum[dst], ex);
}

// ---------------- edge pass 3: g_acc += sum_e (ex/s[dst]) * xl[src] ----------------
__global__ void k_edge3(const void* __restrict__ ei) {
    __shared__ float sg[D];
    int lane = threadIdx.x & 31;
    if (threadIdx.x < D) sg[threadIdx.x] = 0.f;
    __syncthreads();
    int wid = (blockIdx.x * blockDim.x + threadIdx.x) >> 5;
    int nw = (gridDim.x * blockDim.x) >> 5;
    int is64 = d_is64;
    float4 acc = make_float4(0.f, 0.f, 0.f, 0.f);
    const int nbatch = EE / 32;  // 18750, exact
    for (int b = wid; b < nbatch; b += nw) {
        int e = b * 32 + lane;
        int src = eidx(ei, is64, e);
        int dst = eidx(ei, is64, (long long)EE + e);
        float w = d_ew[e] / d_ssum[dst];
#pragma unroll
        for (int t = 0; t < 32; t++) {
            int bs = __shfl_sync(~0u, src, t);
            float bw = __shfl_sync(~0u, w, t);
            float4 v = *(const float4*)(d_xl + (size_t)bs * D + lane * 4);
            acc.x += bw * v.x; acc.y += bw * v.y; acc.z += bw * v.z; acc.w += bw * v.w;
        }
    }
    atomicAdd(&sg[lane * 4 + 0], acc.x);
    atomicAdd(&sg[lane * 4 + 1], acc.y);
    atomicAdd(&sg[lane * 4 + 2], acc.z);
    atomicAdd(&sg[lane * 4 + 3], acc.w);
    __syncthreads();
    if (threadIdx.x < D) atomicAdd(&d_gacc[threadIdx.x], sg[threadIdx.x]);
}

// ---------------- finalize pooled g -> d_inp ----------------
__global__ void k_fing(const float* __restrict__ conv_bias) {
    int t = threadIdx.x;
    if (t < D) d_inp[t] = d_gacc[t] * (1.0f / (float)NMD) + conv_bias[t];
}

// ---------------- LSTM cell + pred layer1 (1 block, 512 threads) ----------------
__global__ void __launch_bounds__(512) k_lstm(
    const float* __restrict__ Wih, const float* __restrict__ Whh,
    const float* __restrict__ bih, const float* __restrict__ bhh,
    const float* __restrict__ W1,  const float* __restrict__ b1,
    float* __restrict__ out) {
    __shared__ float si[D], sh[D], sg[4 * D], snh[D];
    int t = threadIdx.x;
    if (t < D) { si[t] = d_inp[t]; sh[t] = d_h[t]; }
    __syncthreads();
    float acc = bih[t] + bhh[t];
    const float4* wi = (const float4*)(Wih + (size_t)t * D);
    const float4* wh = (const float4*)(Whh + (size_t)t * D);
#pragma unroll 8
    for (int k = 0; k < 32; k++) {
        float4 a = wi[k]; float4 b = wh[k];
        float4 iv = *(const float4*)(si + 4 * k);
        float4 hv = *(const float4*)(sh + 4 * k);
        acc += a.x * iv.x + a.y * iv.y + a.z * iv.z + a.w * iv.w;
        acc += b.x * hv.x + b.y * hv.y + b.z * hv.z + b.w * hv.w;
    }
    sg[t] = acc;
    __syncthreads();
    if (t < D) {
        float ig = 1.f / (1.f + expf(-sg[t]));
        float fg = 1.f / (1.f + expf(-sg[D + t]));
        float gg = tanhf(sg[2 * D + t]);
        float og = 1.f / (1.f + expf(-sg[3 * D + t]));
        float c = fg * d_c[t] + ig * gg;
        float h = og * tanhf(c);
        d_c[t] = c; d_h[t] = h;
        snh[t] = h;
        out[2 * HOR + t] = h;           // h output slot (overwritten each step)
        out[2 * HOR + D + t] = c;       // c output slot
    }
    __syncthreads();
    if (t < D) {
        float a2 = b1[t];
        const float4* w1 = (const float4*)(W1 + (size_t)t * D);
#pragma unroll 8
        for (int k = 0; k < 32; k++) {
            float4 a = w1[k];
            float4 hv = *(const float4*)(snh + 4 * k);
            a2 += a.x * hv.x + a.y * hv.y + a.z * hv.z + a.w * hv.w;
        }
        d_h2[t] = a2 > 0.f ? a2 : 0.f;
    }
}

// ---------------- logits + gumbel + online softmax partials ----------------
__global__ void __launch_bounds__(256) k_logits(const float* __restrict__ W2,
                                                const float* __restrict__ b2, int step) {
    __shared__ float sh2[D];
    __shared__ float wbest[8]; __shared__ int wbi[8];
    __shared__ float wlm[8], wls[8];
    int t = threadIdx.x, lane = t & 31, w = t >> 5;
    if (t < D) sh2[t] = d_h2[t];
    __syncthreads();
    uint2 key = d_keys[step];
    float4 h0 = *(const float4*)(sh2 + lane * 4);
    int wid = (blockIdx.x * blockDim.x + t) >> 5;
    int nw = (gridDim.x * blockDim.x) >> 5;
    float best = -__int_as_float(0x7f800000);  // -inf
    int bi = 0;
    float lm = best;
    float ls = 0.f;
    for (int r = wid; r < NMD; r += nw) {
        float4 wv = *(const float4*)(W2 + (size_t)r * D + lane * 4);
        float p = wv.x * h0.x + wv.y * h0.y + wv.z * h0.z + wv.w * h0.w;
#pragma unroll
        for (int o = 16; o; o >>= 1) p += __shfl_xor_sync(~0u, p, o);
        if (lane == 0) {
            float l = p + b2[r];
            d_logits[r] = l;
            // PARTITIONABLE random_bits(key, 32, (NM,)):
            // counter = (hi32(j), lo32(j)) = (0, j); bits = out.x ^ out.y
            uint2 tr = tf2x32(key.x, key.y, 0u, (unsigned)r);
            unsigned bits = tr.x ^ tr.y;
            float u = __uint_as_float((bits >> 9) | 0x3f800000u) - 1.0f;
            if (u == 0.f) u = 1.17549435e-38f;  // FLT_MIN (JAX tiny clamp)
            float gum = -logf(-logf(u));
            float sc = gum + l;
            if (sc > best) { best = sc; bi = r; }  // rows increasing -> first max = lowest idx
            if (l > lm) { ls = ls * expf(lm - l) + 1.f; lm = l; }
            else        { ls += expf(l - lm); }
        }
    }
    if (lane == 0) { wbest[w] = best; wbi[w] = bi; wlm[w] = lm; wls[w] = ls; }
    __syncthreads();
    if (t == 0) {
        float B = -__int_as_float(0x7f800000); int BI = 0;
        float M = B, S = 0.f;
        for (int i = 0; i < 8; i++) {
            if (wbest[i] > B || (wbest[i] == B && wbi[i] < BI)) { B = wbest[i]; BI = wbi[i]; }
            if (wls[i] > 0.f) {
                if (wlm[i] > M) { S = S * expf(M - wlm[i]) + wls[i]; M = wlm[i]; }
                else            { S += wls[i] * expf(wlm[i] - M); }
            }
        }
        d_pm_best[blockIdx.x] = B; d_pm_bi[blockIdx.x] = BI;
        d_pm_lm[blockIdx.x] = M;  d_pm_ls[blockIdx.x] = S;
    }
}

// ---------------- reduce partials, sample, fetch embedding ----------------
__global__ void k_sample(const float* __restrict__ emb, float* __restrict__ out, int step) {
    __shared__ int sA;
    int t = threadIdx.x;
    if (t == 0) {
        float B = -__int_as_float(0x7f800000); int BI = 0;
        float M = B, S = 0.f;
        for (int i = 0; i < GLOG; i++) {
            float b = d_pm_best[i]; int bidx = d_pm_bi[i];
            if (b > B || (b == B && bidx < BI)) { B = b; BI = bidx; }
            float m = d_pm_lm[i], s = d_pm_ls[i];
            if (s > 0.f) {
                if (m > M) { S = S * expf(M - m) + s; M = m; }
                else       { S += s * expf(m - M); }
            }
        }
        float lp = d_logits[BI] - (M + logf(S));
        out[step] = (float)BI;
        out[HOR + step] = lp;
        sA = BI;
    }
    __syncthreads();
    int a = sA;
    if (t < D) d_inp[t] = emb[(size_t)a * D + t];
}

// ---------------- launch ----------------
extern "C" void kernel_launch(void* const* d_in, const int* in_sizes, int n_in,
                              void* d_out, int out_size) {
    const float* state_features = (const float*)d_in[0];
    const float* model_features = (const float*)d_in[1];
    const void*  edge_index     = d_in[2];
    const float* W_l   = (const float*)d_in[3];
    const float* W_r   = (const float*)d_in[4];
    const float* att   = (const float*)d_in[5];
    const float* cbias = (const float*)d_in[6];
    const float* Wih   = (const float*)d_in[7];
    const float* Whh   = (const float*)d_in[8];
    const float* bih   = (const float*)d_in[9];
    const float* bhh   = (const float*)d_in[10];
    const float* W1    = (const float*)d_in[11];
    const float* b1    = (const float*)d_in[12];
    const float* W2    = (const float*)d_in[13];
    const float* b2    = (const float*)d_in[14];
    const float* emb   = (const float*)d_in[15];
    float* out = (float*)d_out;

    const int smem = (128 * 132 + 64 * 132) * (int)sizeof(float);  // 101376
    static_assert((128 * 132 + 64 * 132) * 4 <= 227 * 1024, "smem");
    cudaFuncSetAttribute(k_gemm, cudaFuncAttributeMaxDynamicSharedMemorySize, smem);

    float* xl = nullptr; float* xr = nullptr;
    cudaGetSymbolAddress((void**)&xl, d_xl);
    cudaGetSymbolAddress((void**)&xr, d_xr);

    k_init<<<(NMD + 255) / 256, 256>>>(edge_index);
    k_gemm<<<(NSN + 63) / 64, 256, smem>>>(state_features, W_l, xl, NSN);
    k_gemm<<<(NMD + 63) / 64, 256, smem>>>(model_features, W_r, xr, NMD);
    k_edge1<<<592, 256>>>(edge_index, att);
    k_edge2<<<(EE + 255) / 256, 256>>>(edge_index);
    k_edge3<<<592, 256>>>(edge_index);
    k_fing<<<1, 128>>>(cbias);
    for (int s = 0; s < HOR; s++) {
        k_lstm<<<1, 512>>>(Wih, Whh, bih, bhh, W1, b1, out);
        k_logits<<<GLOG, 256>>>(W2, b2, s);
        k_sample<<<1, 128>>>(emb, out, s);
    }
    (void)in_sizes; (void)n_in; (void)out_size;
}